// round 1
// baseline (speedup 1.0000x reference)
#include <cuda_runtime.h>
#include <math.h>

#define NN 50000
#define EE 1600000
#define FIN 128
#define HH 256
#define EDM 64
#define NLV 8
#define NGR 64
#define NCLS 10
#define NEG 0.2f

// ---------------- scratch (static device globals; no allocation) ----------------
__device__ float g_ea[EE * EDM];       // edge attrs (layer1, then layer2 in-place)
__device__ float g_xl[NN * HH];
__device__ float g_xr[NN * HH];
__device__ float g_h[NN * HH];
__device__ float g_logits[EE];
__device__ int   g_rowptr[NN + 1];
__device__ int   g_wr[NN];
__device__ int   g_counts[NN];
__device__ int   g_csrsrc[EE];
__device__ int   g_csreid[EE];
__device__ float g_w2w3[512 * EDM];
__device__ float g_bvec[EDM];
__device__ float g_pooled[NGR * HH];

// ---------------- small utility kernels ----------------
__global__ void k_zero_int(int* p, int n) {
    int i = blockIdx.x * blockDim.x + threadIdx.x;
    if (i < n) p[i] = 0;
}
__global__ void k_zero_f(float* p, int n) {
    int i = blockIdx.x * blockDim.x + threadIdx.x;
    if (i < n) p[i] = 0.f;
}

__global__ void k_hist(const int* __restrict__ dst) {
    int e = blockIdx.x * blockDim.x + threadIdx.x;
    if (e < EE) atomicAdd(&g_counts[dst[e]], 1);
}

__global__ void k_scan() {
    __shared__ int wsum[32];
    __shared__ int carry_s;
    int t = threadIdx.x, lane = t & 31, wid = t >> 5;
    if (t == 0) carry_s = 0;
    __syncthreads();
    for (int base = 0; base < NN; base += 1024) {
        int i = base + t;
        int v = (i < NN) ? g_counts[i] : 0;
        int x = v;
        #pragma unroll
        for (int o = 1; o < 32; o <<= 1) {
            int y = __shfl_up_sync(0xffffffffu, x, o);
            if (lane >= o) x += y;
        }
        if (lane == 31) wsum[wid] = x;
        __syncthreads();
        if (wid == 0) {
            int s = wsum[lane];
            #pragma unroll
            for (int o = 1; o < 32; o <<= 1) {
                int y = __shfl_up_sync(0xffffffffu, s, o);
                if (lane >= o) s += y;
            }
            wsum[lane] = s;
        }
        __syncthreads();
        int carry = carry_s;
        int incl = x + ((wid > 0) ? wsum[wid - 1] : 0) + carry;
        if (i < NN) {
            g_rowptr[i] = incl - v;
            g_wr[i]     = incl - v;
        }
        __syncthreads();
        if (t == 1023) carry_s = incl;
        __syncthreads();
    }
    if (threadIdx.x == 0) g_rowptr[NN] = carry_s;
}

__global__ void k_scatter(const int* __restrict__ src, const int* __restrict__ dst) {
    int e = blockIdx.x * blockDim.x + threadIdx.x;
    if (e < EE) {
        int d = dst[e];
        int pos = atomicAdd(&g_wr[d], 1);
        g_csrsrc[pos] = src[e];
        g_csreid[pos] = e;
    }
}

// ---------------- perm-invariant edge MLP ----------------
// ea = relu( [ relu(sort(raw)@w1+b1)@w2+b2 , range, std, max ] @ ws + bs )
// block = 128 threads, tile = 32 edges
__global__ void k_pm(const float* __restrict__ raw,
                     const float* __restrict__ w1, const float* __restrict__ b1,
                     const float* __restrict__ w2, const float* __restrict__ b2,
                     const float* __restrict__ ws, const float* __restrict__ bs,
                     float* __restrict__ ea) {
    extern __shared__ float sm[];
    float* w1s  = sm;               // 8*256   = 2048
    float* wss  = w1s + 2048;       // 67*64   = 4288
    float* b1s  = wss + 4288;       // 256
    float* b2s  = b1s + 256;        // 64
    float* bss  = b2s + 64;         // 64
    float* xs_s = bss + 64;         // 32*8    = 256
    float* comb = xs_s + 256;       // 32*68   = 2176
    float* h1s  = comb + 2176;      // 32*257  = 8224
    int t = threadIdx.x;
    for (int i = t; i < 2048; i += 128) w1s[i] = w1[i];
    for (int i = t; i < 4288; i += 128) wss[i] = ws[i];
    for (int i = t; i < 256; i += 128)  b1s[i] = b1[i];
    if (t < 64) { b2s[t] = b2[t]; bss[t] = bs[t]; }
    __syncthreads();

    int o4 = (t & 15) * 4;       // output col group (4 of 64)
    int m4 = (t >> 4) * 4;       // edge group (4 of 32)
    int ntiles = EE / 32;
    for (int tile = blockIdx.x; tile < ntiles; tile += gridDim.x) {
        int e0 = tile * 32;
        __syncthreads();
        if (t < 32) {
            float a[8];
            #pragma unroll
            for (int k = 0; k < 8; k++) a[k] = raw[(e0 + t) * 8 + k];
            #pragma unroll
            for (int i = 0; i < 7; i++)
                #pragma unroll
                for (int j = 0; j < 7 - i; j++) {
                    float lo = fminf(a[j], a[j + 1]);
                    float hi = fmaxf(a[j], a[j + 1]);
                    a[j] = lo; a[j + 1] = hi;
                }
            float sum = 0.f;
            #pragma unroll
            for (int k = 0; k < 8; k++) { sum += a[k]; xs_s[t * 8 + k] = a[k]; }
            float mean = sum * 0.125f, vs = 0.f;
            #pragma unroll
            for (int k = 0; k < 8; k++) { float d = a[k] - mean; vs += d * d; }
            comb[t * 68 + 64] = a[7] - a[0];
            comb[t * 68 + 65] = sqrtf(vs * (1.0f / 7.0f));
            comb[t * 68 + 66] = a[7];
        }
        __syncthreads();
        // h1 = relu(xs @ w1 + b1)  (32 x 256)
        for (int idx = t; idx < 32 * 256; idx += 128) {
            int m = idx >> 8, j = idx & 255;
            float acc = b1s[j];
            #pragma unroll
            for (int k = 0; k < 8; k++) acc += xs_s[m * 8 + k] * w1s[k * 256 + j];
            h1s[m * 257 + j] = fmaxf(acc, 0.f);
        }
        __syncthreads();
        // f = h1 @ w2 + b2  (32 x 64)
        float acc[4][4];
        #pragma unroll
        for (int i = 0; i < 4; i++)
            #pragma unroll
            for (int j = 0; j < 4; j++) acc[i][j] = 0.f;
        for (int k = 0; k < 256; k++) {
            float4 b = *(const float4*)&w2[k * 64 + o4];
            #pragma unroll
            for (int i = 0; i < 4; i++) {
                float a_ = h1s[(m4 + i) * 257 + k];
                acc[i][0] += a_ * b.x; acc[i][1] += a_ * b.y;
                acc[i][2] += a_ * b.z; acc[i][3] += a_ * b.w;
            }
        }
        #pragma unroll
        for (int i = 0; i < 4; i++)
            #pragma unroll
            for (int j = 0; j < 4; j++)
                comb[(m4 + i) * 68 + o4 + j] = acc[i][j] + b2s[o4 + j];
        __syncthreads();
        // out = relu(comb @ ws + bs)
        #pragma unroll
        for (int i = 0; i < 4; i++)
            #pragma unroll
            for (int j = 0; j < 4; j++) acc[i][j] = bss[o4 + j];
        for (int k = 0; k < 67; k++) {
            float4 b = *(const float4*)&wss[k * 64 + o4];
            #pragma unroll
            for (int i = 0; i < 4; i++) {
                float a_ = comb[(m4 + i) * 68 + k];
                acc[i][0] += a_ * b.x; acc[i][1] += a_ * b.y;
                acc[i][2] += a_ * b.z; acc[i][3] += a_ * b.w;
            }
        }
        #pragma unroll
        for (int i = 0; i < 4; i++) {
            float4 o;
            o.x = fmaxf(acc[i][0], 0.f); o.y = fmaxf(acc[i][1], 0.f);
            o.z = fmaxf(acc[i][2], 0.f); o.w = fmaxf(acc[i][3], 0.f);
            *(float4*)&ea[(e0 + m4 + i) * 64 + o4] = o;
        }
    }
}

// ---------------- node-feature GEMM: C[M x 256] = act(A[M x K]) @ W + bias ----------------
template <int K, bool RELU_IN>
__global__ void k_gemm(const float* __restrict__ A, const float* __restrict__ W,
                       const float* __restrict__ bias, float* __restrict__ C, int M) {
    __shared__ float As[64][33];
    __shared__ float Ws[32][64];
    int t = threadIdx.x;
    int bm = blockIdx.x * 64, bn = blockIdx.y * 64;
    int tx = t & 15, ty = t >> 4;
    float acc[4][4];
    #pragma unroll
    for (int i = 0; i < 4; i++)
        #pragma unroll
        for (int j = 0; j < 4; j++) acc[i][j] = 0.f;
    for (int kb = 0; kb < K; kb += 32) {
        #pragma unroll
        for (int r = 0; r < 8; r++) {
            int idx = t + r * 256;
            int row = idx >> 5, col = idx & 31;
            int grow = bm + row;
            float v = (grow < M) ? A[grow * K + kb + col] : 0.f;
            if (RELU_IN) v = fmaxf(v, 0.f);
            As[row][col] = v;
        }
        #pragma unroll
        for (int r = 0; r < 8; r++) {
            int idx = t + r * 256;
            int row = idx >> 6, col = idx & 63;
            Ws[row][col] = W[(kb + row) * 256 + bn + col];
        }
        __syncthreads();
        #pragma unroll
        for (int k = 0; k < 32; k++) {
            float4 b = *(float4*)&Ws[k][tx * 4];
            float a0 = As[ty * 4 + 0][k], a1 = As[ty * 4 + 1][k];
            float a2 = As[ty * 4 + 2][k], a3 = As[ty * 4 + 3][k];
            acc[0][0] += a0 * b.x; acc[0][1] += a0 * b.y; acc[0][2] += a0 * b.z; acc[0][3] += a0 * b.w;
            acc[1][0] += a1 * b.x; acc[1][1] += a1 * b.y; acc[1][2] += a1 * b.z; acc[1][3] += a1 * b.w;
            acc[2][0] += a2 * b.x; acc[2][1] += a2 * b.y; acc[2][2] += a2 * b.z; acc[2][3] += a2 * b.w;
            acc[3][0] += a3 * b.x; acc[3][1] += a3 * b.y; acc[3][2] += a3 * b.z; acc[3][3] += a3 * b.w;
        }
        __syncthreads();
    }
    #pragma unroll
    for (int i = 0; i < 4; i++) {
        int row = bm + ty * 4 + i;
        if (row < M) {
            float bb0 = 0.f, bb1 = 0.f, bb2 = 0.f, bb3 = 0.f;
            if (bias) {
                bb0 = bias[bn + tx * 4 + 0]; bb1 = bias[bn + tx * 4 + 1];
                bb2 = bias[bn + tx * 4 + 2]; bb3 = bias[bn + tx * 4 + 3];
            }
            float4 o = make_float4(acc[i][0] + bb0, acc[i][1] + bb1,
                                   acc[i][2] + bb2, acc[i][3] + bb3);
            *(float4*)&C[row * 256 + bn + tx * 4] = o;
        }
    }
}

// ---------------- per-edge attention logits ----------------
// logits[e] = sum_c leaky(xl[src,c] + xr[dst,c] + (ea[e]@we)[c]) * att[c]
__global__ void k_elog(const float* __restrict__ ea, const float* __restrict__ we,
                       const float* __restrict__ att, const float* __restrict__ xl,
                       const float* __restrict__ xr, const int* __restrict__ src,
                       const int* __restrict__ dst, float* __restrict__ logits) {
    extern __shared__ float sm[];
    float* wes  = sm;             // 64*256 = 16384
    float* atts = wes + 16384;    // 256
    float* eas  = atts + 256;     // 32*65  = 2080
    float* reds = eas + 2080;     // 64
    int* srcs = (int*)(reds + 64);
    int* dsts = srcs + 32;
    int t = threadIdx.x;
    for (int i = t; i < 16384; i += 256) wes[i] = we[i];
    if (t < 256) atts[t] = att[t];
    __syncthreads();
    int c4 = (t & 63) * 4;
    int mb = (t >> 6) * 8;
    int wid = t >> 5, lane = t & 31;
    int ntiles = EE / 32;
    for (int tile = blockIdx.x; tile < ntiles; tile += gridDim.x) {
        int e0 = tile * 32;
        __syncthreads();
        for (int i = t; i < 32 * 64; i += 256) {
            int m = i >> 6, c = i & 63;
            eas[m * 65 + c] = ea[(e0 + m) * 64 + c];
        }
        if (t < 32) { srcs[t] = src[e0 + t]; dsts[t] = dst[e0 + t]; }
        __syncthreads();
        float acc[8][4];
        #pragma unroll
        for (int i = 0; i < 8; i++)
            #pragma unroll
            for (int j = 0; j < 4; j++) acc[i][j] = 0.f;
        for (int k = 0; k < 64; k++) {
            float4 b = *(float4*)&wes[k * 256 + c4];
            #pragma unroll
            for (int i = 0; i < 8; i++) {
                float a_ = eas[(mb + i) * 65 + k];
                acc[i][0] += a_ * b.x; acc[i][1] += a_ * b.y;
                acc[i][2] += a_ * b.z; acc[i][3] += a_ * b.w;
            }
        }
        #pragma unroll
        for (int i = 0; i < 8; i++) {
            int m = mb + i;
            float4 xlv = *(const float4*)&xl[srcs[m] * 256 + c4];
            float4 xrv = *(const float4*)&xr[dsts[m] * 256 + c4];
            float v0 = acc[i][0] + xlv.x + xrv.x;
            float v1 = acc[i][1] + xlv.y + xrv.y;
            float v2 = acc[i][2] + xlv.z + xrv.z;
            float v3 = acc[i][3] + xlv.w + xrv.w;
            v0 = (v0 > 0.f) ? v0 : NEG * v0;
            v1 = (v1 > 0.f) ? v1 : NEG * v1;
            v2 = (v2 > 0.f) ? v2 : NEG * v2;
            v3 = (v3 > 0.f) ? v3 : NEG * v3;
            float p = v0 * atts[c4] + v1 * atts[c4 + 1] + v2 * atts[c4 + 2] + v3 * atts[c4 + 3];
            #pragma unroll
            for (int o = 16; o > 0; o >>= 1) p += __shfl_xor_sync(0xffffffffu, p, o);
            if (lane == 0) reds[m * 2 + (wid & 1)] = p;
        }
        __syncthreads();
        if (t < 32) logits[e0 + t] = reds[t * 2] + reds[t * 2 + 1];
    }
}

// ---------------- CSR softmax + aggregation (warp per node) ----------------
template <bool RELU_OUT>
__global__ void k_agg(const float* __restrict__ logits, const float* __restrict__ xl,
                      const float* __restrict__ bo, float* __restrict__ out) {
    int w = (blockIdx.x * blockDim.x + threadIdx.x) >> 5;
    int lane = threadIdx.x & 31;
    if (w >= NN) return;
    int beg = g_rowptr[w], end = g_rowptr[w + 1];
    float mx = -1e30f;
    for (int i = beg + lane; i < end; i += 32) mx = fmaxf(mx, logits[g_csreid[i]]);
    #pragma unroll
    for (int o = 16; o > 0; o >>= 1) mx = fmaxf(mx, __shfl_xor_sync(0xffffffffu, mx, o));
    float s = 0.f;
    for (int i = beg + lane; i < end; i += 32) s += __expf(logits[g_csreid[i]] - mx);
    #pragma unroll
    for (int o = 16; o > 0; o >>= 1) s += __shfl_xor_sync(0xffffffffu, s, o);
    float inv = (end > beg) ? 1.0f / s : 0.f;
    float acc[8];
    #pragma unroll
    for (int j = 0; j < 8; j++) acc[j] = 0.f;
    for (int i = beg; i < end; i++) {
        float a = __expf(logits[g_csreid[i]] - mx) * inv;
        const float4* xp = (const float4*)&xl[g_csrsrc[i] * 256 + lane * 8];
        float4 v0 = xp[0], v1 = xp[1];
        acc[0] += a * v0.x; acc[1] += a * v0.y; acc[2] += a * v0.z; acc[3] += a * v0.w;
        acc[4] += a * v1.x; acc[5] += a * v1.y; acc[6] += a * v1.z; acc[7] += a * v1.w;
    }
    float4 o0, o1;
    o0.x = acc[0] + bo[lane * 8 + 0]; o0.y = acc[1] + bo[lane * 8 + 1];
    o0.z = acc[2] + bo[lane * 8 + 2]; o0.w = acc[3] + bo[lane * 8 + 3];
    o1.x = acc[4] + bo[lane * 8 + 4]; o1.y = acc[5] + bo[lane * 8 + 5];
    o1.z = acc[6] + bo[lane * 8 + 6]; o1.w = acc[7] + bo[lane * 8 + 7];
    if (RELU_OUT) {
        o0.x = fmaxf(o0.x, 0.f); o0.y = fmaxf(o0.y, 0.f); o0.z = fmaxf(o0.z, 0.f); o0.w = fmaxf(o0.w, 0.f);
        o1.x = fmaxf(o1.x, 0.f); o1.y = fmaxf(o1.y, 0.f); o1.z = fmaxf(o1.z, 0.f); o1.w = fmaxf(o1.w, 0.f);
    }
    *(float4*)&out[w * 256 + lane * 8] = o0;
    *(float4*)&out[w * 256 + lane * 8 + 4] = o1;
}

// ---------------- precompute W2@W3b fusion ----------------
__global__ void k_w2w3(const float* __restrict__ w2, const float* __restrict__ b2,
                       const float* __restrict__ w3, const float* __restrict__ b3) {
    int i = blockIdx.x * blockDim.x + threadIdx.x;
    if (i < 512 * 64) {
        int k = i >> 6, o = i & 63;
        float acc = 0.f;
        for (int c = 0; c < 64; c++) acc += w2[k * 64 + c] * w3[(64 + c) * 64 + o];
        g_w2w3[i] = acc;
    }
    if (i < 64) {
        float acc = b3[i];
        for (int c = 0; c < 64; c++) acc += b2[c] * w3[(64 + c) * 64 + i];
        g_bvec[i] = acc;
    }
}

// ---------------- edge update: ea' = ea@w3a + [h[src],h[dst]]@(w2@w3b) + bvec ----------------
__global__ void k_msg(const float* __restrict__ h, const float* __restrict__ w3,
                      const int* __restrict__ src, const int* __restrict__ dst,
                      float* __restrict__ ea) {
    extern __shared__ float sm[];
    float* As   = sm;              // 32*513 = 16416
    float* eas  = As + 16416;      // 32*65  = 2080
    float* wts  = eas + 2080;      // 32*64  = 2048
    float* w3as = wts + 2048;      // 64*64  = 4096
    float* bvs  = w3as + 4096;     // 64
    int* srcs = (int*)(bvs + 64);
    int* dsts = srcs + 32;
    int t = threadIdx.x;
    for (int i = t; i < 4096; i += 256) w3as[i] = w3[i];  // rows 0..63 of w3
    if (t < 64) bvs[t] = g_bvec[t];
    __syncthreads();
    int o4 = (t & 15) * 4;
    int mb = (t >> 4) * 2;
    int ntiles = EE / 32;
    for (int tile = blockIdx.x; tile < ntiles; tile += gridDim.x) {
        int e0 = tile * 32;
        __syncthreads();
        if (t < 32) { srcs[t] = src[e0 + t]; dsts[t] = dst[e0 + t]; }
        for (int i = t; i < 32 * 64; i += 256) {
            int m = i >> 6, c = i & 63;
            eas[m * 65 + c] = ea[(e0 + m) * 64 + c];
        }
        __syncthreads();
        for (int slot = t; slot < 32 * 128; slot += 256) {
            int m = slot >> 7, k4 = slot & 127;
            int k = k4 * 4;
            const float* base = (k < 256) ? &h[srcs[m] * 256 + k]
                                          : &h[dsts[m] * 256 + (k - 256)];
            float4 v = *(const float4*)base;
            float* d = &As[m * 513 + k];
            d[0] = v.x; d[1] = v.y; d[2] = v.z; d[3] = v.w;
        }
        float acc[2][4];
        #pragma unroll
        for (int i = 0; i < 2; i++) {
            acc[i][0] = bvs[o4]; acc[i][1] = bvs[o4 + 1];
            acc[i][2] = bvs[o4 + 2]; acc[i][3] = bvs[o4 + 3];
        }
        for (int kb = 0; kb < 512; kb += 32) {
            __syncthreads();
            for (int i = t; i < 2048; i += 256)
                wts[i] = g_w2w3[(kb + (i >> 6)) * 64 + (i & 63)];
            __syncthreads();
            #pragma unroll
            for (int k = 0; k < 32; k++) {
                float4 b = *(float4*)&wts[k * 64 + o4];
                #pragma unroll
                for (int i = 0; i < 2; i++) {
                    float a_ = As[(mb + i) * 513 + kb + k];
                    acc[i][0] += a_ * b.x; acc[i][1] += a_ * b.y;
                    acc[i][2] += a_ * b.z; acc[i][3] += a_ * b.w;
                }
            }
        }
        for (int c = 0; c < 64; c++) {
            float4 b = *(float4*)&w3as[c * 64 + o4];
            #pragma unroll
            for (int i = 0; i < 2; i++) {
                float a_ = eas[(mb + i) * 65 + c];
                acc[i][0] += a_ * b.x; acc[i][1] += a_ * b.y;
                acc[i][2] += a_ * b.z; acc[i][3] += a_ * b.w;
            }
        }
        #pragma unroll
        for (int i = 0; i < 2; i++) {
            *(float4*)&ea[(e0 + mb + i) * 64 + o4] =
                make_float4(acc[i][0], acc[i][1], acc[i][2], acc[i][3]);
        }
    }
}

// ---------------- pooling (batch is sorted) ----------------
__global__ void k_pool(const float* __restrict__ h2, const int* __restrict__ batch) {
    int c = threadIdx.x;  // 256
    int n0 = blockIdx.x * 128;
    if (n0 >= NN) return;
    int n1 = min(n0 + 128, NN);
    int g = batch[n0];
    float acc = 0.f;
    for (int n = n0; n < n1; n++) {
        int gn = batch[n];
        if (gn != g) {
            atomicAdd(&g_pooled[g * 256 + c], acc);
            acc = 0.f;
            g = gn;
        }
        acc += h2[n * 256 + c];
    }
    atomicAdd(&g_pooled[g * 256 + c], acc);
}

// ---------------- final linear + log_softmax ----------------
__global__ void k_final(const float* __restrict__ w1, const float* __restrict__ b1,
                        float* __restrict__ out) {
    __shared__ float lg[NGR][NCLS];
    __shared__ float rowstat[NGR];
    int t = threadIdx.x;  // 640
    int gI = t / 10, o = t % 10;
    if (t < 640) {
        float acc = b1[o];
        for (int k = 0; k < 256; k++) acc += g_pooled[gI * 256 + k] * w1[k * 10 + o];
        lg[gI][o] = acc;
    }
    __syncthreads();
    if (t < 64) {
        float m = lg[t][0];
        for (int o2 = 1; o2 < 10; o2++) m = fmaxf(m, lg[t][o2]);
        float s = 0.f;
        for (int o2 = 0; o2 < 10; o2++) s += expf(lg[t][o2] - m);
        rowstat[t] = m + logf(s);
    }
    __syncthreads();
    if (t < 640) out[gI * 10 + o] = lg[gI][o] - rowstat[gI];
}

// ---------------- launch ----------------
extern "C" void kernel_launch(void* const* d_in, const int* in_sizes, int n_in,
                              void* d_out, int out_size) {
    const float* x        = (const float*)d_in[0];
    const int*   eidx     = (const int*)d_in[1];
    const float* raw      = (const float*)d_in[2];
    const int*   batch    = (const int*)d_in[3];
    const float* pm_w1    = (const float*)d_in[4];
    const float* pm_b1    = (const float*)d_in[5];
    const float* pm_w2    = (const float*)d_in[6];
    const float* pm_b2    = (const float*)d_in[7];
    const float* pm_ws    = (const float*)d_in[8];
    const float* pm_bs    = (const float*)d_in[9];
    const float* g1_wl    = (const float*)d_in[10];
    const float* g1_bl    = (const float*)d_in[11];
    const float* g1_wr    = (const float*)d_in[12];
    const float* g1_we    = (const float*)d_in[13];
    const float* g1_att   = (const float*)d_in[14];
    const float* g1_bo    = (const float*)d_in[15];
    const float* g2_wl    = (const float*)d_in[16];
    const float* g2_bl    = (const float*)d_in[17];
    const float* g2_wr    = (const float*)d_in[18];
    const float* g2_we    = (const float*)d_in[19];
    const float* g2_att   = (const float*)d_in[20];
    const float* g2_bo    = (const float*)d_in[21];
    const float* w2in     = (const float*)d_in[22];
    const float* b2in     = (const float*)d_in[23];
    const float* w3in     = (const float*)d_in[24];
    const float* b3in     = (const float*)d_in[25];
    const float* w1fin    = (const float*)d_in[26];
    const float* b1fin    = (const float*)d_in[27];
    const int* src = eidx;
    const int* dst = eidx + EE;

    float *ea, *xl, *xr, *h, *logits, *pooled;
    int *counts;
    cudaGetSymbolAddress((void**)&ea, g_ea);
    cudaGetSymbolAddress((void**)&xl, g_xl);
    cudaGetSymbolAddress((void**)&xr, g_xr);
    cudaGetSymbolAddress((void**)&h, g_h);
    cudaGetSymbolAddress((void**)&logits, g_logits);
    cudaGetSymbolAddress((void**)&pooled, g_pooled);
    cudaGetSymbolAddress((void**)&counts, g_counts);

    const int PM_SMEM  = (2048 + 4288 + 256 + 64 + 64 + 256 + 2176 + 8224) * 4;
    const int EL_SMEM  = (16384 + 256 + 2080 + 64) * 4 + 64 * 4;
    const int MSG_SMEM = (16416 + 2080 + 2048 + 4096 + 64) * 4 + 64 * 4;
    cudaFuncSetAttribute(k_pm, cudaFuncAttributeMaxDynamicSharedMemorySize, PM_SMEM);
    cudaFuncSetAttribute(k_elog, cudaFuncAttributeMaxDynamicSharedMemorySize, EL_SMEM);
    cudaFuncSetAttribute(k_msg, cudaFuncAttributeMaxDynamicSharedMemorySize, MSG_SMEM);

    // CSR build
    k_zero_int<<<(NN + 255) / 256, 256>>>(counts, NN);
    k_hist<<<EE / 256, 256>>>(dst);
    k_scan<<<1, 1024>>>();
    k_scatter<<<EE / 256, 256>>>(src, dst);

    // edge MLP
    k_pm<<<2048, 128, PM_SMEM>>>(raw, pm_w1, pm_b1, pm_w2, pm_b2, pm_ws, pm_bs, ea);

    // layer 1
    dim3 gg((NN + 63) / 64, 4);
    k_gemm<128, false><<<gg, 256>>>(x, g1_wl, g1_bl, xl, NN);
    k_gemm<128, false><<<gg, 256>>>(x, g1_wr, nullptr, xr, NN);
    k_elog<<<2048, 256, EL_SMEM>>>(ea, g1_we, g1_att, xl, xr, src, dst, logits);
    k_agg<false><<<(NN * 32 + 255) / 256, 256>>>(logits, xl, g1_bo, h);

    // edge update (fused message + w3)
    k_w2w3<<<128, 256>>>(w2in, b2in, w3in, b3in);
    k_msg<<<2048, 256, MSG_SMEM>>>(h, w3in, src, dst, ea);

    // layer 2
    k_gemm<256, true><<<gg, 256>>>(h, g2_wl, g2_bl, xl, NN);
    k_gemm<256, true><<<gg, 256>>>(h, g2_wr, nullptr, xr, NN);
    k_elog<<<2048, 256, EL_SMEM>>>(ea, g2_we, g2_att, xl, xr, src, dst, logits);
    k_agg<true><<<(NN * 32 + 255) / 256, 256>>>(logits, xl, g2_bo, h);

    // pooling + head
    k_zero_f<<<(NGR * 256 + 255) / 256, 256>>>(pooled, NGR * 256);
    k_pool<<<(NN + 127) / 128, 256>>>(h, batch);
    k_final<<<1, 640>>>(w1fin, b1fin, (float*)d_out);
}

// round 5
// speedup vs baseline: 1.1650x; 1.1650x over previous
#include <cuda_runtime.h>
#include <math.h>

#define NN 50000
#define EE 1600000
#define FIN 128
#define HH 256
#define EDM 64
#define NLV 8
#define NGR 64
#define NCLS 10
#define NEG 0.2f

// ---------------- scratch (static device globals; no allocation) ----------------
__device__ float g_ea[EE * EDM];       // layer-1 edge attrs (kept through layer 2)
__device__ float g_xl[NN * HH];        // pure xl (used by agg)
__device__ float g_xr[NN * HH];
__device__ float g_xlog[NN * HH];      // xl + h@WPL   (layer-2 logits only)
__device__ float g_xrog[NN * HH];      // xr + h@WPR + cvec
__device__ float g_h[NN * HH];
__device__ float g_logits[EE];
__device__ int   g_rowptr[NN + 1];
__device__ int   g_wr[NN];
__device__ int   g_counts[NN];
__device__ int   g_csrsrc[EE];
__device__ int   g_csreid[EE];
__device__ float g_tmp1[256 * 64];     // w2a@w3b
__device__ float g_tmp2[256 * 64];     // w2b@w3b
__device__ float g_bsmall[64];         // b3 + b2@w3b
__device__ float g_WPL[256 * 256];     // w2a@w3b@we2
__device__ float g_WPR[256 * 256];     // w2b@w3b@we2
__device__ float g_M[64 * 256];        // w3a@we2
__device__ float g_cvec[256];          // bsmall@we2
__device__ float g_pooled[NGR * HH];

// ---------------- small utility kernels ----------------
__global__ void k_zero_int(int* p, int n) {
    int i = blockIdx.x * blockDim.x + threadIdx.x;
    if (i < n) p[i] = 0;
}
__global__ void k_zero_f(float* p, int n) {
    int i = blockIdx.x * blockDim.x + threadIdx.x;
    if (i < n) p[i] = 0.f;
}

__global__ void k_hist(const int* __restrict__ dst) {
    int e = blockIdx.x * blockDim.x + threadIdx.x;
    if (e < EE) atomicAdd(&g_counts[dst[e]], 1);
}

__global__ void k_scan() {
    __shared__ int wsum[32];
    __shared__ int carry_s;
    int t = threadIdx.x, lane = t & 31, wid = t >> 5;
    if (t == 0) carry_s = 0;
    __syncthreads();
    for (int base = 0; base < NN; base += 1024) {
        int i = base + t;
        int v = (i < NN) ? g_counts[i] : 0;
        int x = v;
        #pragma unroll
        for (int o = 1; o < 32; o <<= 1) {
            int y = __shfl_up_sync(0xffffffffu, x, o);
            if (lane >= o) x += y;
        }
        if (lane == 31) wsum[wid] = x;
        __syncthreads();
        if (wid == 0) {
            int s = wsum[lane];
            #pragma unroll
            for (int o = 1; o < 32; o <<= 1) {
                int y = __shfl_up_sync(0xffffffffu, s, o);
                if (lane >= o) s += y;
            }
            wsum[lane] = s;
        }
        __syncthreads();
        int carry = carry_s;
        int incl = x + ((wid > 0) ? wsum[wid - 1] : 0) + carry;
        if (i < NN) {
            g_rowptr[i] = incl - v;
            g_wr[i]     = incl - v;
        }
        __syncthreads();
        if (t == 1023) carry_s = incl;
        __syncthreads();
    }
    if (threadIdx.x == 0) g_rowptr[NN] = carry_s;
}

__global__ void k_scatter(const int* __restrict__ src, const int* __restrict__ dst) {
    int e = blockIdx.x * blockDim.x + threadIdx.x;
    if (e < EE) {
        int d = dst[e];
        int pos = atomicAdd(&g_wr[d], 1);
        g_csrsrc[pos] = src[e];
        g_csreid[pos] = e;
    }
}

// ---------------- weight-product precompute ----------------
// stage A: tmp1 = w2[0:256]@w3b, tmp2 = w2[256:512]@w3b, bsmall = b3 + b2@w3b
__global__ void k_prep_a(const float* __restrict__ w2, const float* __restrict__ b2,
                         const float* __restrict__ w3, const float* __restrict__ b3) {
    int i = blockIdx.x * blockDim.x + threadIdx.x;
    if (i < 256 * 64) {
        int r = i >> 6, c = i & 63;
        float a1 = 0.f, a2 = 0.f;
        for (int j = 0; j < 64; j++) {
            float w3v = w3[(64 + j) * 64 + c];
            a1 += w2[r * 64 + j] * w3v;
            a2 += w2[(256 + r) * 64 + j] * w3v;
        }
        g_tmp1[i] = a1;
        g_tmp2[i] = a2;
    }
    if (i < 64) {
        float acc = b3[i];
        for (int j = 0; j < 64; j++) acc += b2[j] * w3[(64 + j) * 64 + i];
        g_bsmall[i] = acc;
    }
}

// stage B: WPL = tmp1@we2, WPR = tmp2@we2, M = w3a@we2, cvec = bsmall@we2
__global__ void k_prep_b(const float* __restrict__ w3, const float* __restrict__ we2) {
    int i = blockIdx.x * blockDim.x + threadIdx.x;
    if (i < 256 * 256) {
        int r = i >> 8, c = i & 255;
        float a1 = 0.f, a2 = 0.f;
        for (int j = 0; j < 64; j++) {
            float wv = we2[j * 256 + c];
            a1 += g_tmp1[r * 64 + j] * wv;
            a2 += g_tmp2[r * 64 + j] * wv;
        }
        g_WPL[i] = a1;
        g_WPR[i] = a2;
    }
    if (i < 64 * 256) {
        int r = i >> 8, c = i & 255;
        float acc = 0.f;
        for (int j = 0; j < 64; j++) acc += w3[r * 64 + j] * we2[j * 256 + c];
        g_M[i] = acc;
    }
    if (i < 256) {
        float acc = 0.f;
        for (int j = 0; j < 64; j++) acc += g_bsmall[j] * we2[j * 256 + i];
        g_cvec[i] = acc;
    }
}

// ---------------- perm-invariant edge MLP ----------------
__global__ void k_pm(const float* __restrict__ raw,
                     const float* __restrict__ w1, const float* __restrict__ b1,
                     const float* __restrict__ w2, const float* __restrict__ b2,
                     const float* __restrict__ ws, const float* __restrict__ bs,
                     float* __restrict__ ea) {
    extern __shared__ float sm[];
    float* w1s  = sm;               // 8*256   = 2048
    float* wss  = w1s + 2048;       // 67*64   = 4288
    float* b1s  = wss + 4288;       // 256
    float* b2s  = b1s + 256;        // 64
    float* bss  = b2s + 64;         // 64
    float* xs_s = bss + 64;         // 32*8    = 256
    float* comb = xs_s + 256;       // 32*68   = 2176
    float* h1s  = comb + 2176;      // 32*257  = 8224
    int t = threadIdx.x;
    for (int i = t; i < 2048; i += 128) w1s[i] = w1[i];
    for (int i = t; i < 4288; i += 128) wss[i] = ws[i];
    for (int i = t; i < 256; i += 128)  b1s[i] = b1[i];
    if (t < 64) { b2s[t] = b2[t]; bss[t] = bs[t]; }
    __syncthreads();

    int o4 = (t & 15) * 4;
    int m4 = (t >> 4) * 4;
    int ntiles = EE / 32;
    for (int tile = blockIdx.x; tile < ntiles; tile += gridDim.x) {
        int e0 = tile * 32;
        __syncthreads();
        if (t < 32) {
            float a[8];
            #pragma unroll
            for (int k = 0; k < 8; k++) a[k] = raw[(e0 + t) * 8 + k];
            #pragma unroll
            for (int i = 0; i < 7; i++)
                #pragma unroll
                for (int j = 0; j < 7 - i; j++) {
                    float lo = fminf(a[j], a[j + 1]);
                    float hi = fmaxf(a[j], a[j + 1]);
                    a[j] = lo; a[j + 1] = hi;
                }
            float sum = 0.f;
            #pragma unroll
            for (int k = 0; k < 8; k++) { sum += a[k]; xs_s[t * 8 + k] = a[k]; }
            float mean = sum * 0.125f, vs = 0.f;
            #pragma unroll
            for (int k = 0; k < 8; k++) { float d = a[k] - mean; vs += d * d; }
            comb[t * 68 + 64] = a[7] - a[0];
            comb[t * 68 + 65] = sqrtf(vs * (1.0f / 7.0f));
            comb[t * 68 + 66] = a[7];
        }
        __syncthreads();
        for (int idx = t; idx < 32 * 256; idx += 128) {
            int m = idx >> 8, j = idx & 255;
            float acc = b1s[j];
            #pragma unroll
            for (int k = 0; k < 8; k++) acc += xs_s[m * 8 + k] * w1s[k * 256 + j];
            h1s[m * 257 + j] = fmaxf(acc, 0.f);
        }
        __syncthreads();
        float acc[4][4];
        #pragma unroll
        for (int i = 0; i < 4; i++)
            #pragma unroll
            for (int j = 0; j < 4; j++) acc[i][j] = 0.f;
        for (int k = 0; k < 256; k++) {
            float4 b = *(const float4*)&w2[k * 64 + o4];
            #pragma unroll
            for (int i = 0; i < 4; i++) {
                float a_ = h1s[(m4 + i) * 257 + k];
                acc[i][0] += a_ * b.x; acc[i][1] += a_ * b.y;
                acc[i][2] += a_ * b.z; acc[i][3] += a_ * b.w;
            }
        }
        #pragma unroll
        for (int i = 0; i < 4; i++)
            #pragma unroll
            for (int j = 0; j < 4; j++)
                comb[(m4 + i) * 68 + o4 + j] = acc[i][j] + b2s[o4 + j];
        __syncthreads();
        #pragma unroll
        for (int i = 0; i < 4; i++)
            #pragma unroll
            for (int j = 0; j < 4; j++) acc[i][j] = bss[o4 + j];
        for (int k = 0; k < 67; k++) {
            float4 b = *(const float4*)&wss[k * 64 + o4];
            #pragma unroll
            for (int i = 0; i < 4; i++) {
                float a_ = comb[(m4 + i) * 68 + k];
                acc[i][0] += a_ * b.x; acc[i][1] += a_ * b.y;
                acc[i][2] += a_ * b.z; acc[i][3] += a_ * b.w;
            }
        }
        #pragma unroll
        for (int i = 0; i < 4; i++) {
            float4 o;
            o.x = fmaxf(acc[i][0], 0.f); o.y = fmaxf(acc[i][1], 0.f);
            o.z = fmaxf(acc[i][2], 0.f); o.w = fmaxf(acc[i][3], 0.f);
            *(float4*)&ea[(e0 + m4 + i) * 64 + o4] = o;
        }
    }
}

// ---------------- node-feature GEMM: C[M x NOUT] = act(A[M x K]) @ W (+ bias) (+ addin) ----------------
template <int K, int NOUT, bool RELU_IN, bool HAS_ADD>
__global__ void k_gemm(const float* __restrict__ A, const float* __restrict__ W,
                       const float* __restrict__ bias, const float* __restrict__ addin,
                       float* __restrict__ C, int M) {
    __shared__ float As[64][33];
    __shared__ float Ws[32][64];
    int t = threadIdx.x;
    int bm = blockIdx.x * 64, bn = blockIdx.y * 64;
    int tx = t & 15, ty = t >> 4;
    float acc[4][4];
    #pragma unroll
    for (int i = 0; i < 4; i++)
        #pragma unroll
        for (int j = 0; j < 4; j++) acc[i][j] = 0.f;
    for (int kb = 0; kb < K; kb += 32) {
        #pragma unroll
        for (int r = 0; r < 8; r++) {
            int idx = t + r * 256;
            int row = idx >> 5, col = idx & 31;
            int grow = bm + row;
            float v = (grow < M) ? A[grow * K + kb + col] : 0.f;
            if (RELU_IN) v = fmaxf(v, 0.f);
            As[row][col] = v;
        }
        #pragma unroll
        for (int r = 0; r < 8; r++) {
            int idx = t + r * 256;
            int row = idx >> 6, col = idx & 63;
            Ws[row][col] = W[(kb + row) * NOUT + bn + col];
        }
        __syncthreads();
        #pragma unroll
        for (int k = 0; k < 32; k++) {
            float4 b = *(float4*)&Ws[k][tx * 4];
            float a0 = As[ty * 4 + 0][k], a1 = As[ty * 4 + 1][k];
            float a2 = As[ty * 4 + 2][k], a3 = As[ty * 4 + 3][k];
            acc[0][0] += a0 * b.x; acc[0][1] += a0 * b.y; acc[0][2] += a0 * b.z; acc[0][3] += a0 * b.w;
            acc[1][0] += a1 * b.x; acc[1][1] += a1 * b.y; acc[1][2] += a1 * b.z; acc[1][3] += a1 * b.w;
            acc[2][0] += a2 * b.x; acc[2][1] += a2 * b.y; acc[2][2] += a2 * b.z; acc[2][3] += a2 * b.w;
            acc[3][0] += a3 * b.x; acc[3][1] += a3 * b.y; acc[3][2] += a3 * b.z; acc[3][3] += a3 * b.w;
        }
        __syncthreads();
    }
    #pragma unroll
    for (int i = 0; i < 4; i++) {
        int row = bm + ty * 4 + i;
        if (row < M) {
            float4 add = make_float4(0.f, 0.f, 0.f, 0.f);
            if (bias) {
                add.x = bias[bn + tx * 4 + 0]; add.y = bias[bn + tx * 4 + 1];
                add.z = bias[bn + tx * 4 + 2]; add.w = bias[bn + tx * 4 + 3];
            }
            if (HAS_ADD) {
                float4 av = *(const float4*)&addin[row * NOUT + bn + tx * 4];
                add.x += av.x; add.y += av.y; add.z += av.z; add.w += av.w;
            }
            float4 o = make_float4(acc[i][0] + add.x, acc[i][1] + add.y,
                                   acc[i][2] + add.z, acc[i][3] + add.w);
            *(float4*)&C[row * NOUT + bn + tx * 4] = o;
        }
    }
}

// ---------------- per-edge attention logits ----------------
__global__ void k_elog(const float* __restrict__ ea, const float* __restrict__ we,
                       const float* __restrict__ att, const float* __restrict__ xl,
                       const float* __restrict__ xr, const int* __restrict__ src,
                       const int* __restrict__ dst, float* __restrict__ logits) {
    extern __shared__ float sm[];
    float* wes  = sm;             // 64*256 = 16384
    float* atts = wes + 16384;    // 256
    float* eas  = atts + 256;     // 32*65  = 2080
    float* reds = eas + 2080;     // 64
    int* srcs = (int*)(reds + 64);
    int* dsts = srcs + 32;
    int t = threadIdx.x;
    for (int i = t; i < 16384; i += 256) wes[i] = we[i];
    if (t < 256) atts[t] = att[t];
    __syncthreads();
    int c4 = (t & 63) * 4;
    int mb = (t >> 6) * 8;
    int wid = t >> 5, lane = t & 31;
    int ntiles = EE / 32;
    for (int tile = blockIdx.x; tile < ntiles; tile += gridDim.x) {
        int e0 = tile * 32;
        __syncthreads();
        for (int i = t; i < 32 * 64; i += 256) {
            int m = i >> 6, c = i & 63;
            eas[m * 65 + c] = ea[(e0 + m) * 64 + c];
        }
        if (t < 32) { srcs[t] = src[e0 + t]; dsts[t] = dst[e0 + t]; }
        __syncthreads();
        float acc[8][4];
        #pragma unroll
        for (int i = 0; i < 8; i++)
            #pragma unroll
            for (int j = 0; j < 4; j++) acc[i][j] = 0.f;
        for (int k = 0; k < 64; k++) {
            float4 b = *(float4*)&wes[k * 256 + c4];
            #pragma unroll
            for (int i = 0; i < 8; i++) {
                float a_ = eas[(mb + i) * 65 + k];
                acc[i][0] += a_ * b.x; acc[i][1] += a_ * b.y;
                acc[i][2] += a_ * b.z; acc[i][3] += a_ * b.w;
            }
        }
        #pragma unroll
        for (int i = 0; i < 8; i++) {
            int m = mb + i;
            float4 xlv = *(const float4*)&xl[srcs[m] * 256 + c4];
            float4 xrv = *(const float4*)&xr[dsts[m] * 256 + c4];
            float v0 = acc[i][0] + xlv.x + xrv.x;
            float v1 = acc[i][1] + xlv.y + xrv.y;
            float v2 = acc[i][2] + xlv.z + xrv.z;
            float v3 = acc[i][3] + xlv.w + xrv.w;
            v0 = (v0 > 0.f) ? v0 : NEG * v0;
            v1 = (v1 > 0.f) ? v1 : NEG * v1;
            v2 = (v2 > 0.f) ? v2 : NEG * v2;
            v3 = (v3 > 0.f) ? v3 : NEG * v3;
            float p = v0 * atts[c4] + v1 * atts[c4 + 1] + v2 * atts[c4 + 2] + v3 * atts[c4 + 3];
            #pragma unroll
            for (int o = 16; o > 0; o >>= 1) p += __shfl_xor_sync(0xffffffffu, p, o);
            if (lane == 0) reds[m * 2 + (wid & 1)] = p;
        }
        __syncthreads();
        if (t < 32) logits[e0 + t] = reds[t * 2] + reds[t * 2 + 1];
    }
}

// ---------------- CSR softmax + aggregation (warp per node) ----------------
template <bool RELU_OUT>
__global__ void k_agg(const float* __restrict__ logits, const float* __restrict__ xl,
                      const float* __restrict__ bo, float* __restrict__ out) {
    int w = (blockIdx.x * blockDim.x + threadIdx.x) >> 5;
    int lane = threadIdx.x & 31;
    if (w >= NN) return;
    int beg = g_rowptr[w], end = g_rowptr[w + 1];
    float mx = -1e30f;
    for (int i = beg + lane; i < end; i += 32) mx = fmaxf(mx, logits[g_csreid[i]]);
    #pragma unroll
    for (int o = 16; o > 0; o >>= 1) mx = fmaxf(mx, __shfl_xor_sync(0xffffffffu, mx, o));
    float s = 0.f;
    for (int i = beg + lane; i < end; i += 32) s += __expf(logits[g_csreid[i]] - mx);
    #pragma unroll
    for (int o = 16; o > 0; o >>= 1) s += __shfl_xor_sync(0xffffffffu, s, o);
    float inv = (end > beg) ? 1.0f / s : 0.f;
    float acc[8];
    #pragma unroll
    for (int j = 0; j < 8; j++) acc[j] = 0.f;
    for (int i = beg; i < end; i++) {
        float a = __expf(logits[g_csreid[i]] - mx) * inv;
        const float4* xp = (const float4*)&xl[g_csrsrc[i] * 256 + lane * 8];
        float4 v0 = xp[0], v1 = xp[1];
        acc[0] += a * v0.x; acc[1] += a * v0.y; acc[2] += a * v0.z; acc[3] += a * v0.w;
        acc[4] += a * v1.x; acc[5] += a * v1.y; acc[6] += a * v1.z; acc[7] += a * v1.w;
    }
    float4 o0, o1;
    o0.x = acc[0] + bo[lane * 8 + 0]; o0.y = acc[1] + bo[lane * 8 + 1];
    o0.z = acc[2] + bo[lane * 8 + 2]; o0.w = acc[3] + bo[lane * 8 + 3];
    o1.x = acc[4] + bo[lane * 8 + 4]; o1.y = acc[5] + bo[lane * 8 + 5];
    o1.z = acc[6] + bo[lane * 8 + 6]; o1.w = acc[7] + bo[lane * 8 + 7];
    if (RELU_OUT) {
        o0.x = fmaxf(o0.x, 0.f); o0.y = fmaxf(o0.y, 0.f); o0.z = fmaxf(o0.z, 0.f); o0.w = fmaxf(o0.w, 0.f);
        o1.x = fmaxf(o1.x, 0.f); o1.y = fmaxf(o1.y, 0.f); o1.z = fmaxf(o1.z, 0.f); o1.w = fmaxf(o1.w, 0.f);
    }
    *(float4*)&out[w * 256 + lane * 8] = o0;
    *(float4*)&out[w * 256 + lane * 8 + 4] = o1;
}

// ---------------- pooling (batch is sorted) ----------------
__global__ void k_pool(const float* __restrict__ h2, const int* __restrict__ batch) {
    int c = threadIdx.x;  // 256
    int n0 = blockIdx.x * 128;
    if (n0 >= NN) return;
    int n1 = min(n0 + 128, NN);
    int g = batch[n0];
    float acc = 0.f;
    for (int n = n0; n < n1; n++) {
        int gn = batch[n];
        if (gn != g) {
            atomicAdd(&g_pooled[g * 256 + c], acc);
            acc = 0.f;
            g = gn;
        }
        acc += h2[n * 256 + c];
    }
    atomicAdd(&g_pooled[g * 256 + c], acc);
}

// ---------------- final linear + log_softmax ----------------
__global__ void k_final(const float* __restrict__ w1, const float* __restrict__ b1,
                        float* __restrict__ out) {
    __shared__ float lg[NGR][NCLS];
    __shared__ float rowstat[NGR];
    int t = threadIdx.x;  // 640
    int gI = t / 10, o = t % 10;
    if (t < 640) {
        float acc = b1[o];
        for (int k = 0; k < 256; k++) acc += g_pooled[gI * 256 + k] * w1[k * 10 + o];
        lg[gI][o] = acc;
    }
    __syncthreads();
    if (t < 64) {
        float m = lg[t][0];
        for (int o2 = 1; o2 < 10; o2++) m = fmaxf(m, lg[t][o2]);
        float s = 0.f;
        for (int o2 = 0; o2 < 10; o2++) s += expf(lg[t][o2] - m);
        rowstat[t] = m + logf(s);
    }
    __syncthreads();
    if (t < 640) out[gI * 10 + o] = lg[gI][o] - rowstat[gI];
}

// ---------------- launch ----------------
extern "C" void kernel_launch(void* const* d_in, const int* in_sizes, int n_in,
                              void* d_out, int out_size) {
    const float* x        = (const float*)d_in[0];
    const int*   eidx     = (const int*)d_in[1];
    const float* raw      = (const float*)d_in[2];
    const int*   batch    = (const int*)d_in[3];
    const float* pm_w1    = (const float*)d_in[4];
    const float* pm_b1    = (const float*)d_in[5];
    const float* pm_w2    = (const float*)d_in[6];
    const float* pm_b2    = (const float*)d_in[7];
    const float* pm_ws    = (const float*)d_in[8];
    const float* pm_bs    = (const float*)d_in[9];
    const float* g1_wl    = (const float*)d_in[10];
    const float* g1_bl    = (const float*)d_in[11];
    const float* g1_wr    = (const float*)d_in[12];
    const float* g1_we    = (const float*)d_in[13];
    const float* g1_att   = (const float*)d_in[14];
    const float* g1_bo    = (const float*)d_in[15];
    const float* g2_wl    = (const float*)d_in[16];
    const float* g2_bl    = (const float*)d_in[17];
    const float* g2_wr    = (const float*)d_in[18];
    const float* g2_we    = (const float*)d_in[19];
    const float* g2_att   = (const float*)d_in[20];
    const float* g2_bo    = (const float*)d_in[21];
    const float* w2in     = (const float*)d_in[22];
    const float* b2in     = (const float*)d_in[23];
    const float* w3in     = (const float*)d_in[24];
    const float* b3in     = (const float*)d_in[25];
    const float* w1fin    = (const float*)d_in[26];
    const float* b1fin    = (const float*)d_in[27];
    const int* src = eidx;
    const int* dst = eidx + EE;

    float *ea, *xl, *xr, *xlog, *xrog, *h, *logits, *pooled;
    float *WPL, *WPR, *Mmat, *cvec;
    int *counts;
    cudaGetSymbolAddress((void**)&ea, g_ea);
    cudaGetSymbolAddress((void**)&xl, g_xl);
    cudaGetSymbolAddress((void**)&xr, g_xr);
    cudaGetSymbolAddress((void**)&xlog, g_xlog);
    cudaGetSymbolAddress((void**)&xrog, g_xrog);
    cudaGetSymbolAddress((void**)&h, g_h);
    cudaGetSymbolAddress((void**)&logits, g_logits);
    cudaGetSymbolAddress((void**)&pooled, g_pooled);
    cudaGetSymbolAddress((void**)&counts, g_counts);
    cudaGetSymbolAddress((void**)&WPL, g_WPL);
    cudaGetSymbolAddress((void**)&WPR, g_WPR);
    cudaGetSymbolAddress((void**)&Mmat, g_M);
    cudaGetSymbolAddress((void**)&cvec, g_cvec);

    const int PM_SMEM  = (2048 + 4288 + 256 + 64 + 64 + 256 + 2176 + 8224) * 4;
    const int EL_SMEM  = (16384 + 256 + 2080 + 64) * 4 + 64 * 4;
    cudaFuncSetAttribute(k_pm, cudaFuncAttributeMaxDynamicSharedMemorySize, PM_SMEM);
    cudaFuncSetAttribute(k_elog, cudaFuncAttributeMaxDynamicSharedMemorySize, EL_SMEM);

    // CSR build
    k_zero_int<<<(NN + 255) / 256, 256>>>(counts, NN);
    k_hist<<<EE / 256, 256>>>(dst);
    k_scan<<<1, 1024>>>();
    k_scatter<<<EE / 256, 256>>>(src, dst);

    // weight-product precompute (independent of graph data)
    k_prep_a<<<(256 * 64 + 255) / 256, 256>>>(w2in, b2in, w3in, b3in);
    k_prep_b<<<(256 * 256 + 255) / 256, 256>>>(w3in, g2_we);

    // edge MLP -> ea1
    k_pm<<<2048, 128, PM_SMEM>>>(raw, pm_w1, pm_b1, pm_w2, pm_b2, pm_ws, pm_bs, ea);

    // layer 1
    dim3 gg((NN + 63) / 64, 4);
    k_gemm<128, 256, false, false><<<gg, 256>>>(x, g1_wl, g1_bl, nullptr, xl, NN);
    k_gemm<128, 256, false, false><<<gg, 256>>>(x, g1_wr, nullptr, nullptr, xr, NN);
    k_elog<<<2048, 256, EL_SMEM>>>(ea, g1_we, g1_att, xl, xr, src, dst, logits);
    k_agg<false><<<(NN * 32 + 255) / 256, 256>>>(logits, xl, g1_bo, h);

    // layer 2 (edge_attr2 is never materialized; its effect is folded into
    // xlog/xrog node arrays and the M weight used by k_elog)
    k_gemm<256, 256, true,  false><<<gg, 256>>>(h, g2_wl, g2_bl, nullptr, xl, NN);
    k_gemm<256, 256, true,  false><<<gg, 256>>>(h, g2_wr, nullptr, nullptr, xr, NN);
    k_gemm<256, 256, false, true ><<<gg, 256>>>(h, WPL, nullptr, xl, xlog, NN);
    k_gemm<256, 256, false, true ><<<gg, 256>>>(h, WPR, cvec, xr, xrog, NN);
    k_elog<<<2048, 256, EL_SMEM>>>(ea, Mmat, g2_att, xlog, xrog, src, dst, logits);
    k_agg<true><<<(NN * 32 + 255) / 256, 256>>>(logits, xl, g2_bo, h);

    // pooling + head
    k_zero_f<<<(NGR * 256 + 255) / 256, 256>>>(pooled, NGR * 256);
    k_pool<<<(NN + 127) / 128, 256>>>(h, batch);
    k_final<<<1, 640>>>(w1fin, b1fin, (float*)d_out);
}

// round 7
// speedup vs baseline: 1.5524x; 1.3325x over previous
#include <cuda_runtime.h>
#include <math.h>

#define NN 50000
#define EE 1600000
#define FIN 128
#define HH 256
#define EDM 64
#define NLV 8
#define NGR 64
#define NCLS 10
#define NEG 0.2f

typedef unsigned long long u64;

__device__ __forceinline__ void fma2(u64& acc, u64 a, u64 b) {
    asm("fma.rn.f32x2 %0, %1, %2, %3;" : "=l"(acc) : "l"(a), "l"(b), "l"(acc));
}
__device__ __forceinline__ u64 pack2(float x, float y) {
    u64 r;
    asm("mov.b64 %0, {%1, %2};" : "=l"(r) : "f"(x), "f"(y));
    return r;
}
__device__ __forceinline__ float2 unpack2(u64 v) {
    float2 r;
    asm("mov.b64 {%0, %1}, %2;" : "=f"(r.x), "=f"(r.y) : "l"(v));
    return r;
}

// ---------------- scratch (static device globals; no allocation) ----------------
__device__ float g_ea[EE * EDM];       // layer-1 edge attrs (kept through layer 2)
__device__ float g_xl[NN * HH];        // pure xl (used by agg)
__device__ float g_xr[NN * HH];
__device__ float g_xlog[NN * HH];      // xl + h@WPL   (layer-2 logits only)
__device__ float g_xrog[NN * HH];      // xr + h@WPR + cvec
__device__ float g_h[NN * HH];
__device__ float g_logits[EE];
__device__ int   g_rowptr[NN + 1];
__device__ int   g_wr[NN];
__device__ int   g_counts[NN];
__device__ int   g_csrsrc[EE];
__device__ int   g_csreid[EE];
__device__ float g_tmp1[256 * 64];     // w2a@w3b
__device__ float g_tmp2[256 * 64];     // w2b@w3b
__device__ float g_bsmall[64];         // b3 + b2@w3b
__device__ float g_WPL[256 * 256];     // w2a@w3b@we2
__device__ float g_WPR[256 * 256];     // w2b@w3b@we2
__device__ float g_M[64 * 256];        // w3a@we2
__device__ float g_cvec[256];          // bsmall@we2
__device__ float g_pooled[NGR * HH];

// ---------------- small utility kernels ----------------
__global__ void k_zero_int(int* p, int n) {
    int i = blockIdx.x * blockDim.x + threadIdx.x;
    if (i < n) p[i] = 0;
}
__global__ void k_zero_f(float* p, int n) {
    int i = blockIdx.x * blockDim.x + threadIdx.x;
    if (i < n) p[i] = 0.f;
}

__global__ void k_hist(const int* __restrict__ dst) {
    int e = blockIdx.x * blockDim.x + threadIdx.x;
    if (e < EE) atomicAdd(&g_counts[dst[e]], 1);
}

__global__ void k_scan() {
    __shared__ int wsum[32];
    __shared__ int carry_s;
    int t = threadIdx.x, lane = t & 31, wid = t >> 5;
    if (t == 0) carry_s = 0;
    __syncthreads();
    for (int base = 0; base < NN; base += 1024) {
        int i = base + t;
        int v = (i < NN) ? g_counts[i] : 0;
        int x = v;
        #pragma unroll
        for (int o = 1; o < 32; o <<= 1) {
            int y = __shfl_up_sync(0xffffffffu, x, o);
            if (lane >= o) x += y;
        }
        if (lane == 31) wsum[wid] = x;
        __syncthreads();
        if (wid == 0) {
            int s = wsum[lane];
            #pragma unroll
            for (int o = 1; o < 32; o <<= 1) {
                int y = __shfl_up_sync(0xffffffffu, s, o);
                if (lane >= o) s += y;
            }
            wsum[lane] = s;
        }
        __syncthreads();
        int carry = carry_s;
        int incl = x + ((wid > 0) ? wsum[wid - 1] : 0) + carry;
        if (i < NN) {
            g_rowptr[i] = incl - v;
            g_wr[i]     = incl - v;
        }
        __syncthreads();
        if (t == 1023) carry_s = incl;
        __syncthreads();
    }
    if (threadIdx.x == 0) g_rowptr[NN] = carry_s;
}

__global__ void k_scatter(const int* __restrict__ src, const int* __restrict__ dst) {
    int e = blockIdx.x * blockDim.x + threadIdx.x;
    if (e < EE) {
        int d = dst[e];
        int pos = atomicAdd(&g_wr[d], 1);
        g_csrsrc[pos] = src[e];
        g_csreid[pos] = e;
    }
}

// ---------------- weight-product precompute ----------------
__global__ void k_prep_a(const float* __restrict__ w2, const float* __restrict__ b2,
                         const float* __restrict__ w3, const float* __restrict__ b3) {
    int i = blockIdx.x * blockDim.x + threadIdx.x;
    if (i < 256 * 64) {
        int r = i >> 6, c = i & 63;
        float a1 = 0.f, a2 = 0.f;
        for (int j = 0; j < 64; j++) {
            float w3v = w3[(64 + j) * 64 + c];
            a1 += w2[r * 64 + j] * w3v;
            a2 += w2[(256 + r) * 64 + j] * w3v;
        }
        g_tmp1[i] = a1;
        g_tmp2[i] = a2;
    }
    if (i < 64) {
        float acc = b3[i];
        for (int j = 0; j < 64; j++) acc += b2[j] * w3[(64 + j) * 64 + i];
        g_bsmall[i] = acc;
    }
}

__global__ void k_prep_b(const float* __restrict__ w3, const float* __restrict__ we2) {
    int i = blockIdx.x * blockDim.x + threadIdx.x;
    if (i < 256 * 256) {
        int r = i >> 8, c = i & 255;
        float a1 = 0.f, a2 = 0.f;
        for (int j = 0; j < 64; j++) {
            float wv = we2[j * 256 + c];
            a1 += g_tmp1[r * 64 + j] * wv;
            a2 += g_tmp2[r * 64 + j] * wv;
        }
        g_WPL[i] = a1;
        g_WPR[i] = a2;
    }
    if (i < 64 * 256) {
        int r = i >> 8, c = i & 255;
        float acc = 0.f;
        for (int j = 0; j < 64; j++) acc += w3[r * 64 + j] * we2[j * 256 + c];
        g_M[i] = acc;
    }
    if (i < 256) {
        float acc = 0.f;
        for (int j = 0; j < 64; j++) acc += g_bsmall[j] * we2[j * 256 + i];
        g_cvec[i] = acc;
    }
}

// ---------------- perm-invariant edge MLP ----------------
__global__ void k_pm(const float* __restrict__ raw,
                     const float* __restrict__ w1, const float* __restrict__ b1,
                     const float* __restrict__ w2, const float* __restrict__ b2,
                     const float* __restrict__ ws, const float* __restrict__ bs,
                     float* __restrict__ ea) {
    extern __shared__ float sm[];
    float* w1s  = sm;               // 8*256   = 2048
    float* wss  = w1s + 2048;       // 67*64   = 4288
    float* b1s  = wss + 4288;       // 256
    float* b2s  = b1s + 256;        // 64
    float* bss  = b2s + 64;         // 64
    float* xs_s = bss + 64;         // 32*8    = 256
    float* comb = xs_s + 256;       // 32*68   = 2176
    float* h1t  = comb + 2176;      // 256*34  = 8704  (transposed: [k][m], stride 34)
    int t = threadIdx.x;
    for (int i = t; i < 2048; i += 128) w1s[i] = w1[i];
    for (int i = t; i < 4288; i += 128) wss[i] = ws[i];
    for (int i = t; i < 256; i += 128)  b1s[i] = b1[i];
    if (t < 64) { b2s[t] = b2[t]; bss[t] = bs[t]; }
    __syncthreads();

    int o4 = (t & 15) * 4;
    int m4 = (t >> 4) * 4;
    int ntiles = EE / 32;
    for (int tile = blockIdx.x; tile < ntiles; tile += gridDim.x) {
        int e0 = tile * 32;
        __syncthreads();
        if (t < 32) {
            float a[8];
            #pragma unroll
            for (int k = 0; k < 8; k++) a[k] = raw[(e0 + t) * 8 + k];
            #pragma unroll
            for (int i = 0; i < 7; i++)
                #pragma unroll
                for (int j = 0; j < 7 - i; j++) {
                    float lo = fminf(a[j], a[j + 1]);
                    float hi = fmaxf(a[j], a[j + 1]);
                    a[j] = lo; a[j + 1] = hi;
                }
            float sum = 0.f;
            #pragma unroll
            for (int k = 0; k < 8; k++) { sum += a[k]; xs_s[t * 8 + k] = a[k]; }
            float mean = sum * 0.125f, vs = 0.f;
            #pragma unroll
            for (int k = 0; k < 8; k++) { float d = a[k] - mean; vs += d * d; }
            comb[t * 68 + 64] = a[7] - a[0];
            comb[t * 68 + 65] = sqrtf(vs * (1.0f / 7.0f));
            comb[t * 68 + 66] = a[7];
        }
        __syncthreads();
        // h1t[j][m] = relu(xs[m] @ w1[:,j] + b1[j])   (transposed store)
        for (int idx = t; idx < 32 * 256; idx += 128) {
            int m = idx >> 8, j = idx & 255;
            float acc = b1s[j];
            #pragma unroll
            for (int k = 0; k < 8; k++) acc += xs_s[m * 8 + k] * w1s[k * 256 + j];
            h1t[j * 34 + m] = fmaxf(acc, 0.f);
        }
        __syncthreads();
        // f = h1 @ w2 + b2  (32 x 64)  -- f32x2: edge-pairs from transposed h1t
        {
            u64 acc2[2][4];
            #pragma unroll
            for (int p = 0; p < 2; p++)
                #pragma unroll
                for (int j = 0; j < 4; j++) acc2[p][j] = 0ull;
            for (int k = 0; k < 256; k++) {
                float4 b = *(const float4*)&w2[k * 64 + o4];
                u64 bd0 = pack2(b.x, b.x), bd1 = pack2(b.y, b.y);
                u64 bd2 = pack2(b.z, b.z), bd3 = pack2(b.w, b.w);
                u64 a0 = *(const u64*)&h1t[k * 34 + m4];
                u64 a1 = *(const u64*)&h1t[k * 34 + m4 + 2];
                fma2(acc2[0][0], a0, bd0); fma2(acc2[0][1], a0, bd1);
                fma2(acc2[0][2], a0, bd2); fma2(acc2[0][3], a0, bd3);
                fma2(acc2[1][0], a1, bd0); fma2(acc2[1][1], a1, bd1);
                fma2(acc2[1][2], a1, bd2); fma2(acc2[1][3], a1, bd3);
            }
            #pragma unroll
            for (int p = 0; p < 2; p++)
                #pragma unroll
                for (int j = 0; j < 4; j++) {
                    float2 v = unpack2(acc2[p][j]);
                    comb[(m4 + 2 * p + 0) * 68 + o4 + j] = v.x + b2s[o4 + j];
                    comb[(m4 + 2 * p + 1) * 68 + o4 + j] = v.y + b2s[o4 + j];
                }
        }
        __syncthreads();
        // out = relu(comb @ ws + bs)
        float acc[4][4];
        #pragma unroll
        for (int i = 0; i < 4; i++)
            #pragma unroll
            for (int j = 0; j < 4; j++) acc[i][j] = bss[o4 + j];
        for (int k = 0; k < 67; k++) {
            float4 b = *(const float4*)&wss[k * 64 + o4];
            #pragma unroll
            for (int i = 0; i < 4; i++) {
                float a_ = comb[(m4 + i) * 68 + k];
                acc[i][0] += a_ * b.x; acc[i][1] += a_ * b.y;
                acc[i][2] += a_ * b.z; acc[i][3] += a_ * b.w;
            }
        }
        #pragma unroll
        for (int i = 0; i < 4; i++) {
            float4 o;
            o.x = fmaxf(acc[i][0], 0.f); o.y = fmaxf(acc[i][1], 0.f);
            o.z = fmaxf(acc[i][2], 0.f); o.w = fmaxf(acc[i][3], 0.f);
            *(float4*)&ea[(e0 + m4 + i) * 64 + o4] = o;
        }
    }
}

// ---------------- node-feature GEMM: C[M x NOUT] = act(A[M x K]) @ W (+ bias) (+ addin) ----------------
// f32x2 inner loop: A stored duplicated (u64, both halves equal), W read as col-pairs.
template <int K, int NOUT, bool RELU_IN, bool HAS_ADD>
__global__ void k_gemm(const float* __restrict__ A, const float* __restrict__ W,
                       const float* __restrict__ bias, const float* __restrict__ addin,
                       float* __restrict__ C, int M) {
    __shared__ u64 As2[32 * 65];     // [k][row], stride 65 u64
    __shared__ float Ws[32][64];
    int t = threadIdx.x;
    int bm = blockIdx.x * 64, bn = blockIdx.y * 64;
    int tx = t & 15, ty = t >> 4;
    u64 acc2[4][2];
    #pragma unroll
    for (int i = 0; i < 4; i++) { acc2[i][0] = 0ull; acc2[i][1] = 0ull; }
    for (int kb = 0; kb < K; kb += 32) {
        #pragma unroll
        for (int r = 0; r < 8; r++) {
            int idx = t + r * 256;
            int row = idx >> 5, col = idx & 31;
            int grow = bm + row;
            float v = (grow < M) ? A[grow * K + kb + col] : 0.f;
            if (RELU_IN) v = fmaxf(v, 0.f);
            As2[col * 65 + row] = pack2(v, v);
        }
        #pragma unroll
        for (int r = 0; r < 8; r++) {
            int idx = t + r * 256;
            int row = idx >> 6, col = idx & 63;
            Ws[row][col] = W[(kb + row) * NOUT + bn + col];
        }
        __syncthreads();
        #pragma unroll
        for (int k = 0; k < 32; k++) {
            ulonglong2 b = *(ulonglong2*)&Ws[k][tx * 4];
            u64 a0 = As2[k * 65 + ty * 4 + 0];
            u64 a1 = As2[k * 65 + ty * 4 + 1];
            u64 a2_ = As2[k * 65 + ty * 4 + 2];
            u64 a3 = As2[k * 65 + ty * 4 + 3];
            fma2(acc2[0][0], a0, b.x); fma2(acc2[0][1], a0, b.y);
            fma2(acc2[1][0], a1, b.x); fma2(acc2[1][1], a1, b.y);
            fma2(acc2[2][0], a2_, b.x); fma2(acc2[2][1], a2_, b.y);
            fma2(acc2[3][0], a3, b.x); fma2(acc2[3][1], a3, b.y);
        }
        __syncthreads();
    }
    #pragma unroll
    for (int i = 0; i < 4; i++) {
        int row = bm + ty * 4 + i;
        if (row < M) {
            float2 p0 = unpack2(acc2[i][0]);
            float2 p1 = unpack2(acc2[i][1]);
            float4 add = make_float4(0.f, 0.f, 0.f, 0.f);
            if (bias) {
                add.x = bias[bn + tx * 4 + 0]; add.y = bias[bn + tx * 4 + 1];
                add.z = bias[bn + tx * 4 + 2]; add.w = bias[bn + tx * 4 + 3];
            }
            if (HAS_ADD) {
                float4 av = *(const float4*)&addin[row * NOUT + bn + tx * 4];
                add.x += av.x; add.y += av.y; add.z += av.z; add.w += av.w;
            }
            float4 o = make_float4(p0.x + add.x, p0.y + add.y,
                                   p1.x + add.z, p1.y + add.w);
            *(float4*)&C[row * NOUT + bn + tx * 4] = o;
        }
    }
}

// ---------------- per-edge attention logits ----------------
// f32x2 inner: ea tile duplicated in smem (u64 both halves), we read as ulonglong2 col-pairs.
__global__ void k_elog(const float* __restrict__ ea, const float* __restrict__ we,
                       const float* __restrict__ att, const float* __restrict__ xl,
                       const float* __restrict__ xr, const int* __restrict__ src,
                       const int* __restrict__ dst, float* __restrict__ logits) {
    extern __shared__ float sm[];
    float* wes  = sm;                        // 64*256 = 16384 floats
    float* atts = wes + 16384;               // 256
    float* reds = atts + 256;                // 64
    int* srcs = (int*)(reds + 64);           // 32
    int* dsts = srcs + 32;                   // 32
    u64* eas2 = (u64*)(dsts + 32);           // 32*68 u64 (offset 67072 B, 8-aligned)
    int t = threadIdx.x;
    for (int i = t; i < 16384; i += 256) wes[i] = we[i];
    if (t < 256) atts[t] = att[t];
    __syncthreads();
    int c4 = (t & 63) * 4;
    int mb = (t >> 6) * 8;
    int wid = t >> 5, lane = t & 31;
    int ntiles = EE / 32;
    for (int tile = blockIdx.x; tile < ntiles; tile += gridDim.x) {
        int e0 = tile * 32;
        __syncthreads();
        for (int i = t; i < 32 * 64; i += 256) {
            int m = i >> 6, c = i & 63;
            float v = ea[(e0 + m) * 64 + c];
            eas2[m * 68 + c] = pack2(v, v);
        }
        if (t < 32) { srcs[t] = src[e0 + t]; dsts[t] = dst[e0 + t]; }
        __syncthreads();
        u64 acc2[8][2];
        #pragma unroll
        for (int i = 0; i < 8; i++) { acc2[i][0] = 0ull; acc2[i][1] = 0ull; }
        for (int k = 0; k < 64; k++) {
            ulonglong2 b = *(ulonglong2*)&wes[k * 256 + c4];
            #pragma unroll
            for (int i = 0; i < 8; i++) {
                u64 a2 = eas2[(mb + i) * 68 + k];
                fma2(acc2[i][0], a2, b.x);
                fma2(acc2[i][1], a2, b.y);
            }
        }
        #pragma unroll
        for (int i = 0; i < 8; i++) {
            int m = mb + i;
            float2 p0 = unpack2(acc2[i][0]);
            float2 p1 = unpack2(acc2[i][1]);
            float4 xlv = *(const float4*)&xl[srcs[m] * 256 + c4];
            float4 xrv = *(const float4*)&xr[dsts[m] * 256 + c4];
            float v0 = p0.x + xlv.x + xrv.x;
            float v1 = p0.y + xlv.y + xrv.y;
            float v2 = p1.x + xlv.z + xrv.z;
            float v3 = p1.y + xlv.w + xrv.w;
            v0 = (v0 > 0.f) ? v0 : NEG * v0;
            v1 = (v1 > 0.f) ? v1 : NEG * v1;
            v2 = (v2 > 0.f) ? v2 : NEG * v2;
            v3 = (v3 > 0.f) ? v3 : NEG * v3;
            float p = v0 * atts[c4] + v1 * atts[c4 + 1] + v2 * atts[c4 + 2] + v3 * atts[c4 + 3];
            #pragma unroll
            for (int o = 16; o > 0; o >>= 1) p += __shfl_xor_sync(0xffffffffu, p, o);
            if (lane == 0) reds[m * 2 + (wid & 1)] = p;
        }
        __syncthreads();
        if (t < 32) logits[e0 + t] = reds[t * 2] + reds[t * 2 + 1];
    }
}

// ---------------- CSR softmax + aggregation (warp per node) ----------------
template <bool RELU_OUT>
__global__ void k_agg(const float* __restrict__ logits, const float* __restrict__ xl,
                      const float* __restrict__ bo, float* __restrict__ out) {
    int w = (blockIdx.x * blockDim.x + threadIdx.x) >> 5;
    int lane = threadIdx.x & 31;
    if (w >= NN) return;
    int beg = g_rowptr[w], end = g_rowptr[w + 1];
    float mx = -1e30f;
    for (int i = beg + lane; i < end; i += 32) mx = fmaxf(mx, logits[g_csreid[i]]);
    #pragma unroll
    for (int o = 16; o > 0; o >>= 1) mx = fmaxf(mx, __shfl_xor_sync(0xffffffffu, mx, o));
    float s = 0.f;
    for (int i = beg + lane; i < end; i += 32) s += __expf(logits[g_csreid[i]] - mx);
    #pragma unroll
    for (int o = 16; o > 0; o >>= 1) s += __shfl_xor_sync(0xffffffffu, s, o);
    float inv = (end > beg) ? 1.0f / s : 0.f;
    float acc[8];
    #pragma unroll
    for (int j = 0; j < 8; j++) acc[j] = 0.f;
    for (int i = beg; i < end; i++) {
        float a = __expf(logits[g_csreid[i]] - mx) * inv;
        const float4* xp = (const float4*)&xl[g_csrsrc[i] * 256 + lane * 8];
        float4 v0 = xp[0], v1 = xp[1];
        acc[0] += a * v0.x; acc[1] += a * v0.y; acc[2] += a * v0.z; acc[3] += a * v0.w;
        acc[4] += a * v1.x; acc[5] += a * v1.y; acc[6] += a * v1.z; acc[7] += a * v1.w;
    }
    float4 o0, o1;
    o0.x = acc[0] + bo[lane * 8 + 0]; o0.y = acc[1] + bo[lane * 8 + 1];
    o0.z = acc[2] + bo[lane * 8 + 2]; o0.w = acc[3] + bo[lane * 8 + 3];
    o1.x = acc[4] + bo[lane * 8 + 4]; o1.y = acc[5] + bo[lane * 8 + 5];
    o1.z = acc[6] + bo[lane * 8 + 6]; o1.w = acc[7] + bo[lane * 8 + 7];
    if (RELU_OUT) {
        o0.x = fmaxf(o0.x, 0.f); o0.y = fmaxf(o0.y, 0.f); o0.z = fmaxf(o0.z, 0.f); o0.w = fmaxf(o0.w, 0.f);
        o1.x = fmaxf(o1.x, 0.f); o1.y = fmaxf(o1.y, 0.f); o1.z = fmaxf(o1.z, 0.f); o1.w = fmaxf(o1.w, 0.f);
    }
    *(float4*)&out[w * 256 + lane * 8] = o0;
    *(float4*)&out[w * 256 + lane * 8 + 4] = o1;
}

// ---------------- pooling (batch is sorted) ----------------
__global__ void k_pool(const float* __restrict__ h2, const int* __restrict__ batch) {
    int c = threadIdx.x;  // 256
    int n0 = blockIdx.x * 128;
    if (n0 >= NN) return;
    int n1 = min(n0 + 128, NN);
    int g = batch[n0];
    float acc = 0.f;
    for (int n = n0; n < n1; n++) {
        int gn = batch[n];
        if (gn != g) {
            atomicAdd(&g_pooled[g * 256 + c], acc);
            acc = 0.f;
            g = gn;
        }
        acc += h2[n * 256 + c];
    }
    atomicAdd(&g_pooled[g * 256 + c], acc);
}

// ---------------- final linear + log_softmax ----------------
__global__ void k_final(const float* __restrict__ w1, const float* __restrict__ b1,
                        float* __restrict__ out) {
    __shared__ float lg[NGR][NCLS];
    __shared__ float rowstat[NGR];
    int t = threadIdx.x;  // 640
    int gI = t / 10, o = t % 10;
    if (t < 640) {
        float acc = b1[o];
        for (int k = 0; k < 256; k++) acc += g_pooled[gI * 256 + k] * w1[k * 10 + o];
        lg[gI][o] = acc;
    }
    __syncthreads();
    if (t < 64) {
        float m = lg[t][0];
        for (int o2 = 1; o2 < 10; o2++) m = fmaxf(m, lg[t][o2]);
        float s = 0.f;
        for (int o2 = 0; o2 < 10; o2++) s += expf(lg[t][o2] - m);
        rowstat[t] = m + logf(s);
    }
    __syncthreads();
    if (t < 640) out[gI * 10 + o] = lg[gI][o] - rowstat[gI];
}

// ---------------- launch ----------------
extern "C" void kernel_launch(void* const* d_in, const int* in_sizes, int n_in,
                              void* d_out, int out_size) {
    const float* x        = (const float*)d_in[0];
    const int*   eidx     = (const int*)d_in[1];
    const float* raw      = (const float*)d_in[2];
    const int*   batch    = (const int*)d_in[3];
    const float* pm_w1    = (const float*)d_in[4];
    const float* pm_b1    = (const float*)d_in[5];
    const float* pm_w2    = (const float*)d_in[6];
    const float* pm_b2    = (const float*)d_in[7];
    const float* pm_ws    = (const float*)d_in[8];
    const float* pm_bs    = (const float*)d_in[9];
    const float* g1_wl    = (const float*)d_in[10];
    const float* g1_bl    = (const float*)d_in[11];
    const float* g1_wr    = (const float*)d_in[12];
    const float* g1_we    = (const float*)d_in[13];
    const float* g1_att   = (const float*)d_in[14];
    const float* g1_bo    = (const float*)d_in[15];
    const float* g2_wl    = (const float*)d_in[16];
    const float* g2_bl    = (const float*)d_in[17];
    const float* g2_wr    = (const float*)d_in[18];
    const float* g2_we    = (const float*)d_in[19];
    const float* g2_att   = (const float*)d_in[20];
    const float* g2_bo    = (const float*)d_in[21];
    const float* w2in     = (const float*)d_in[22];
    const float* b2in     = (const float*)d_in[23];
    const float* w3in     = (const float*)d_in[24];
    const float* b3in     = (const float*)d_in[25];
    const float* w1fin    = (const float*)d_in[26];
    const float* b1fin    = (const float*)d_in[27];
    const int* src = eidx;
    const int* dst = eidx + EE;

    float *ea, *xl, *xr, *xlog, *xrog, *h, *logits, *pooled;
    float *WPL, *WPR, *Mmat, *cvec;
    int *counts;
    cudaGetSymbolAddress((void**)&ea, g_ea);
    cudaGetSymbolAddress((void**)&xl, g_xl);
    cudaGetSymbolAddress((void**)&xr, g_xr);
    cudaGetSymbolAddress((void**)&xlog, g_xlog);
    cudaGetSymbolAddress((void**)&xrog, g_xrog);
    cudaGetSymbolAddress((void**)&h, g_h);
    cudaGetSymbolAddress((void**)&logits, g_logits);
    cudaGetSymbolAddress((void**)&pooled, g_pooled);
    cudaGetSymbolAddress((void**)&counts, g_counts);
    cudaGetSymbolAddress((void**)&WPL, g_WPL);
    cudaGetSymbolAddress((void**)&WPR, g_WPR);
    cudaGetSymbolAddress((void**)&Mmat, g_M);
    cudaGetSymbolAddress((void**)&cvec, g_cvec);

    const int PM_SMEM  = (2048 + 4288 + 256 + 64 + 64 + 256 + 2176 + 8704) * 4;
    const int EL_SMEM  = (16384 + 256 + 64) * 4 + 64 * 4 + 32 * 68 * 8;
    cudaFuncSetAttribute(k_pm, cudaFuncAttributeMaxDynamicSharedMemorySize, PM_SMEM);
    cudaFuncSetAttribute(k_elog, cudaFuncAttributeMaxDynamicSharedMemorySize, EL_SMEM);

    // CSR build
    k_zero_int<<<(NN + 255) / 256, 256>>>(counts, NN);
    k_hist<<<EE / 256, 256>>>(dst);
    k_scan<<<1, 1024>>>();
    k_scatter<<<EE / 256, 256>>>(src, dst);

    // weight-product precompute (independent of graph data)
    k_prep_a<<<(256 * 64 + 255) / 256, 256>>>(w2in, b2in, w3in, b3in);
    k_prep_b<<<(256 * 256 + 255) / 256, 256>>>(w3in, g2_we);

    // edge MLP -> ea1
    k_pm<<<2048, 128, PM_SMEM>>>(raw, pm_w1, pm_b1, pm_w2, pm_b2, pm_ws, pm_bs, ea);

    // layer 1
    dim3 gg((NN + 63) / 64, 4);
    k_gemm<128, 256, false, false><<<gg, 256>>>(x, g1_wl, g1_bl, nullptr, xl, NN);
    k_gemm<128, 256, false, false><<<gg, 256>>>(x, g1_wr, nullptr, nullptr, xr, NN);
    k_elog<<<2048, 256, EL_SMEM>>>(ea, g1_we, g1_att, xl, xr, src, dst, logits);
    k_agg<false><<<(NN * 32 + 255) / 256, 256>>>(logits, xl, g1_bo, h);

    // layer 2 (edge_attr2 never materialized; folded into xlog/xrog and M)
    k_gemm<256, 256, true,  false><<<gg, 256>>>(h, g2_wl, g2_bl, nullptr, xl, NN);
    k_gemm<256, 256, true,  false><<<gg, 256>>>(h, g2_wr, nullptr, nullptr, xr, NN);
    k_gemm<256, 256, false, true ><<<gg, 256>>>(h, WPL, nullptr, xl, xlog, NN);
    k_gemm<256, 256, false, true ><<<gg, 256>>>(h, WPR, cvec, xr, xrog, NN);
    k_elog<<<2048, 256, EL_SMEM>>>(ea, Mmat, g2_att, xlog, xrog, src, dst, logits);
    k_agg<true><<<(NN * 32 + 255) / 256, 256>>>(logits, xl, g2_bo, h);

    // pooling + head
    k_zero_f<<<(NGR * 256 + 255) / 256, 256>>>(pooled, NGR * 256);
    k_pool<<<(NN + 127) / 128, 256>>>(h, batch);
    k_final<<<1, 640>>>(w1fin, b1fin, (float*)d_out);
}